// round 3
// baseline (speedup 1.0000x reference)
#include <cuda_runtime.h>
#include <cstdint>

#define IM 1024
#define NSEG 128
#define EPSF 1e-10f
#define BLOCK 128   // render block (== NSEG)
#define PPT 8       // pixels per thread along y (4 packed pairs)
#define NPAIR (PPT / 2)
#define RGRID ((IM / BLOCK) * (IM / PPT))   // 1024 render blocks
#define NBLOCK 256  // normalize block

typedef unsigned long long u64;

// Per-render-block min/max scratch (no init needed: every slot written each call).
__device__ float g_bmin[RGRID];
__device__ float g_bmax[RGRID];

__device__ __forceinline__ u64 pk2(float lo, float hi) {
    u64 r; asm("mov.b64 %0, {%1, %2};" : "=l"(r) : "f"(lo), "f"(hi)); return r;
}
__device__ __forceinline__ void upk2(u64 v, float& lo, float& hi) {
    asm("mov.b64 {%0, %1}, %2;" : "=f"(lo), "=f"(hi) : "l"(v));
}
__device__ __forceinline__ u64 fma2(u64 a, u64 b, u64 c) {
    u64 r; asm("fma.rn.f32x2 %0, %1, %2, %3;" : "=l"(r) : "l"(a), "l"(b), "l"(c)); return r;
}
__device__ __forceinline__ u64 add2(u64 a, u64 b) {
    u64 r; asm("add.rn.f32x2 %0, %1, %2;" : "=l"(r) : "l"(a), "l"(b)); return r;
}
__device__ __forceinline__ float fsqrt_approx(float x) {
    float r; asm("sqrt.approx.f32 %0, %1;" : "=f"(r) : "f"(x)); return r;
}

__global__ void __launch_bounds__(BLOCK)
sk_render_kernel(const float* __restrict__ xs, const float* __restrict__ ys,
                 float* __restrict__ out) {
    // Packed-duplicated per-segment constants:
    //   sC1[k] = (ay2 = {-y0,-y0}, aw2 = {dyi,dyi})
    //   sC2[k] = (bx2 = {-dx,-dx}, by2 = {-dy,-dy})
    //   sS[k]  = (-x0, dxi)        dxi = dx*invd, dyi = dy*invd
    __shared__ ulonglong2 sC1[NSEG];
    __shared__ ulonglong2 sC2[NSEG];
    __shared__ float2     sS[NSEG];
    __shared__ float s_wmin[BLOCK / 32], s_wmax[BLOCK / 32];

    const int tid = threadIdx.x;

    {
        float x0 = xs[tid], x1 = xs[tid + 1];
        float y0 = ys[tid], y1 = ys[tid + 1];
        float dx = x1 - x0;
        float dy = y1 - y0;
        float invd = 1.0f / (fmaf(dx, dx, dy * dy) + EPSF);
        sC1[tid] = make_ulonglong2(pk2(-y0, -y0), pk2(dy * invd, dy * invd));
        sC2[tid] = make_ulonglong2(pk2(-dx, -dx), pk2(-dy, -dy));
        sS[tid]  = make_float2(-x0, dx * invd);
    }
    __syncthreads();

    // 8 blocks across x (128 cols each), 128 block-rows across y (PPT=8 rows).
    const int bx = blockIdx.x & 7;
    const int by = blockIdx.x >> 3;
    const int x  = bx * BLOCK + tid;
    const int y0i = by * PPT;
    const float xp = (float)x;
    const u64 eps2 = pk2(EPSF, EPSF);

    u64 yp2[NPAIR];
    float acc[PPT];
#pragma unroll
    for (int p = 0; p < NPAIR; p++) {
        yp2[p] = pk2((float)(y0i + 2 * p), (float)(y0i + 2 * p + 1));
        acc[2 * p] = 0.0f; acc[2 * p + 1] = 0.0f;
    }

#pragma unroll 2
    for (int k = 0; k < NSEG; k++) {
        const ulonglong2 c1 = sC1[k];   // (ay2, aw2)
        const ulonglong2 c2 = sC2[k];   // (bx2, by2)
        const float2 s = sS[k];         // (-x0, dxi)
        const float txk = xp + s.x;     // xp - x0
        const float qxi = txk * s.y;    // (xp-x0)*dx*invd
        const u64 txk2 = pk2(txk, txk);
        const u64 qxi2 = pk2(qxi, qxi);

#pragma unroll
        for (int p = 0; p < NPAIR; p++) {
            u64 yd2 = add2(yp2[p], c1.x);            // yp - y0 (pair)
            u64 t2  = fma2(yd2, c1.y, qxi2);          // raw t   (pair)
            float tl, th;
            upk2(t2, tl, th);
            tl = fminf(fmaxf(tl, 0.0f), 1.0f);        // FMNMX (alu pipe)
            th = fminf(fmaxf(th, 0.0f), 1.0f);
            u64 ts2 = pk2(tl, th);
            u64 ex2 = fma2(ts2, c2.x, txk2);          // xp - (x0 + t*dx)
            u64 ey2 = fma2(ts2, c2.y, yd2);           // yp - (y0 + t*dy)
            u64 d2  = fma2(ey2, ey2, eps2);
            d2      = fma2(ex2, ex2, d2);
            float dl, dh;
            upk2(d2, dl, dh);
            acc[2 * p]     += fsqrt_approx(dl);
            acc[2 * p + 1] += fsqrt_approx(dh);
        }
    }

    // Write sums + local min/max
    float lmin = acc[0], lmax = acc[0];
#pragma unroll
    for (int j = 0; j < PPT; j++) {
        out[(y0i + j) * IM + x] = acc[j];
        lmin = fminf(lmin, acc[j]);
        lmax = fmaxf(lmax, acc[j]);
    }

#pragma unroll
    for (int off = 16; off > 0; off >>= 1) {
        lmin = fminf(lmin, __shfl_xor_sync(0xFFFFFFFFu, lmin, off));
        lmax = fmaxf(lmax, __shfl_xor_sync(0xFFFFFFFFu, lmax, off));
    }
    const int lane = tid & 31;
    const int warp = tid >> 5;
    if (lane == 0) { s_wmin[warp] = lmin; s_wmax[warp] = lmax; }
    __syncthreads();
    if (tid == 0) {
        float bmin = s_wmin[0], bmax = s_wmax[0];
#pragma unroll
        for (int w = 1; w < BLOCK / 32; w++) {
            bmin = fminf(bmin, s_wmin[w]);
            bmax = fmaxf(bmax, s_wmax[w]);
        }
        g_bmin[blockIdx.x] = bmin;
        g_bmax[blockIdx.x] = bmax;
    }
}

__global__ void __launch_bounds__(NBLOCK)
sk_normalize_kernel(float* __restrict__ out) {
    __shared__ float s_wmin[NBLOCK / 32], s_wmax[NBLOCK / 32];
    __shared__ float s_min, s_max;
    const int tid = threadIdx.x;

    // Redundant per-block reduction of the 1024 block min/max pairs (L2-hot).
    float lmin = g_bmin[tid], lmax = g_bmax[tid];
#pragma unroll
    for (int i = 1; i < RGRID / NBLOCK; i++) {
        lmin = fminf(lmin, g_bmin[tid + i * NBLOCK]);
        lmax = fmaxf(lmax, g_bmax[tid + i * NBLOCK]);
    }
#pragma unroll
    for (int off = 16; off > 0; off >>= 1) {
        lmin = fminf(lmin, __shfl_xor_sync(0xFFFFFFFFu, lmin, off));
        lmax = fmaxf(lmax, __shfl_xor_sync(0xFFFFFFFFu, lmax, off));
    }
    const int lane = tid & 31;
    const int warp = tid >> 5;
    if (lane == 0) { s_wmin[warp] = lmin; s_wmax[warp] = lmax; }
    __syncthreads();
    if (tid == 0) {
        float bmin = s_wmin[0], bmax = s_wmax[0];
#pragma unroll
        for (int w = 1; w < NBLOCK / 32; w++) {
            bmin = fminf(bmin, s_wmin[w]);
            bmax = fmaxf(bmax, s_wmax[w]);
        }
        s_min = bmin; s_max = bmax;
    }
    __syncthreads();

    const float tmin = s_min;
    const float sc = 1.0f / (s_max - tmin);
    const int i = blockIdx.x * NBLOCK + tid;  // one float4 per thread
    float4* p = reinterpret_cast<float4*>(out) + i;
    float4 v = *p;
    v.x = (v.x - tmin) * sc;
    v.y = (v.y - tmin) * sc;
    v.z = (v.z - tmin) * sc;
    v.w = (v.w - tmin) * sc;
    *p = v;
}

extern "C" void kernel_launch(void* const* d_in, const int* in_sizes, int n_in,
                              void* d_out, int out_size) {
    const float* xs = (const float*)d_in[0];
    const float* ys = (const float*)d_in[1];
    float* out = (float*)d_out;

    sk_render_kernel<<<RGRID, BLOCK>>>(xs, ys, out);
    sk_normalize_kernel<<<(IM * IM) / (4 * NBLOCK), NBLOCK>>>(out);
}

// round 4
// speedup vs baseline: 1.1012x; 1.1012x over previous
#include <cuda_runtime.h>
#include <cuda_fp16.h>
#include <cstdint>

#define IM 1024
#define NSEG 128
#define BLOCK 128   // render block (== NSEG)
#define PPT 8       // pixels per thread along y (4 half2 pairs)
#define NPAIR (PPT / 2)
#define RGRID ((IM / BLOCK) * (IM / PPT))   // 1024 render blocks
#define NBLOCK 256  // normalize block
#define SCALE (1.0f / 64.0f)   // work in 1/64 px units (output is scale-invariant)

// Per-render-block min/max scratch; every slot written each call (no init needed).
__device__ float g_bmin[RGRID];
__device__ float g_bmax[RGRID];
__device__ float2 g_minscale;          // (tmin, 1/(tmax-tmin))
__device__ unsigned g_ticket;          // zero-init at load; self-wraps to 0 per call

struct __align__(16) SegH {
    __half2 ny0;   // broadcast(-y0*S)
    __half2 dyi;   // broadcast(dy*invd)  (invd in scaled units)
    __half2 ndx;   // broadcast(-dx*S)
    __half2 ndy;   // broadcast(-dy*S)
};

__device__ __forceinline__ float fsqrt_approx(float x) {
    float r; asm("sqrt.approx.f32 %0, %1;" : "=f"(r) : "f"(x)); return r;
}

__global__ void __launch_bounds__(BLOCK)
sk_render_kernel(const float* __restrict__ xs, const float* __restrict__ ys,
                 float* __restrict__ out) {
    __shared__ SegH  sH[NSEG];
    __shared__ float2 sF[NSEG];        // (-x0*S, dx*invd)
    __shared__ float s_wmin[BLOCK / 32], s_wmax[BLOCK / 32];
    __shared__ bool s_last;

    const int tid = threadIdx.x;

    {
        float x0 = xs[tid] * SCALE, x1 = xs[tid + 1] * SCALE;
        float y0 = ys[tid] * SCALE, y1 = ys[tid + 1] * SCALE;
        float dx = x1 - x0;
        float dy = y1 - y0;
        float invd = 1.0f / (fmaf(dx, dx, dy * dy) + 1e-12f);
        SegH h;
        h.ny0 = __float2half2_rn(-y0);
        h.dyi = __float2half2_rn(dy * invd);
        h.ndx = __float2half2_rn(-dx);
        h.ndy = __float2half2_rn(-dy);
        sH[tid] = h;
        sF[tid] = make_float2(-x0, dx * invd);
    }
    __syncthreads();

    // 8 blocks across x (128 cols each), 128 block-rows across y (PPT=8 rows).
    const int bx = blockIdx.x & 7;
    const int by = blockIdx.x >> 3;
    const int x  = bx * BLOCK + tid;
    const int y0i = by * PPT;
    const float xp = (float)x * SCALE;

    __half2 yp2[NPAIR];
    float acc[PPT];
#pragma unroll
    for (int p = 0; p < NPAIR; p++) {
        yp2[p] = __floats2half2_rn((float)(y0i + 2 * p) * SCALE,
                                   (float)(y0i + 2 * p + 1) * SCALE);
        acc[2 * p] = 0.0f; acc[2 * p + 1] = 0.0f;
    }

#pragma unroll 2
    for (int k = 0; k < NSEG; k++) {
        const SegH h = sH[k];
        const float2 f = sF[k];
        const float txk = xp + f.x;            // (xp - x0), scaled, fp32
        const float qxi = txk * f.y;           // (xp-x0)*dx*invd
        const __half2 txk2 = __float2half2_rn(txk);
        const __half2 qxi2 = __float2half2_rn(qxi);

#pragma unroll
        for (int p = 0; p < NPAIR; p++) {
            __half2 yd = __hadd2(yp2[p], h.ny0);            // yp - y0
            __half2 t  = __hfma2_sat(yd, h.dyi, qxi2);      // clamp(t,0,1)
            __half2 ex = __hfma2(t, h.ndx, txk2);           // xp - (x0+t*dx)
            __half2 ey = __hfma2(t, h.ndy, yd);             // yp - (y0+t*dy)
            __half2 dq = __hmul2(ey, ey);
            __half2 d2 = __hfma2(ex, ex, dq);
            float dl = __low2float(d2);
            float dh = __high2float(d2);
            acc[2 * p]     += fsqrt_approx(dl);
            acc[2 * p + 1] += fsqrt_approx(dh);
        }
    }

    // Write sums + local min/max
    float lmin = acc[0], lmax = acc[0];
#pragma unroll
    for (int j = 0; j < PPT; j++) {
        out[(y0i + j) * IM + x] = acc[j];
        lmin = fminf(lmin, acc[j]);
        lmax = fmaxf(lmax, acc[j]);
    }

#pragma unroll
    for (int off = 16; off > 0; off >>= 1) {
        lmin = fminf(lmin, __shfl_xor_sync(0xFFFFFFFFu, lmin, off));
        lmax = fmaxf(lmax, __shfl_xor_sync(0xFFFFFFFFu, lmax, off));
    }
    const int lane = tid & 31;
    const int warp = tid >> 5;
    if (lane == 0) { s_wmin[warp] = lmin; s_wmax[warp] = lmax; }
    __syncthreads();
    if (tid == 0) {
        float bmin = s_wmin[0], bmax = s_wmax[0];
#pragma unroll
        for (int w = 1; w < BLOCK / 32; w++) {
            bmin = fminf(bmin, s_wmin[w]);
            bmax = fmaxf(bmax, s_wmax[w]);
        }
        g_bmin[blockIdx.x] = bmin;
        g_bmax[blockIdx.x] = bmax;
        __threadfence();
        unsigned ticket = atomicInc(&g_ticket, RGRID - 1);  // wraps to 0 -> deterministic
        s_last = (ticket == RGRID - 1);
    }
    __syncthreads();

    // Last block reduces all 1024 block results -> (tmin, scale)
    if (s_last) {
        volatile float* vmin = g_bmin;
        volatile float* vmax = g_bmax;
        float m0 = vmin[tid], m1 = vmax[tid];
#pragma unroll
        for (int i = 1; i < RGRID / BLOCK; i++) {
            m0 = fminf(m0, vmin[tid + i * BLOCK]);
            m1 = fmaxf(m1, vmax[tid + i * BLOCK]);
        }
#pragma unroll
        for (int off = 16; off > 0; off >>= 1) {
            m0 = fminf(m0, __shfl_xor_sync(0xFFFFFFFFu, m0, off));
            m1 = fmaxf(m1, __shfl_xor_sync(0xFFFFFFFFu, m1, off));
        }
        if (lane == 0) { s_wmin[warp] = m0; s_wmax[warp] = m1; }
        __syncthreads();
        if (tid == 0) {
            float bmin = s_wmin[0], bmax = s_wmax[0];
#pragma unroll
            for (int w = 1; w < BLOCK / 32; w++) {
                bmin = fminf(bmin, s_wmin[w]);
                bmax = fmaxf(bmax, s_wmax[w]);
            }
            g_minscale = make_float2(bmin, 1.0f / (bmax - bmin));
        }
    }
}

__global__ void __launch_bounds__(NBLOCK)
sk_normalize_kernel(float* __restrict__ out) {
    const float2 ms = g_minscale;
    const float tmin = ms.x, sc = ms.y;
    const int i = blockIdx.x * NBLOCK + threadIdx.x;  // one float4 per thread
    float4* p = reinterpret_cast<float4*>(out) + i;
    float4 v = *p;
    v.x = (v.x - tmin) * sc;
    v.y = (v.y - tmin) * sc;
    v.z = (v.z - tmin) * sc;
    v.w = (v.w - tmin) * sc;
    *p = v;
}

extern "C" void kernel_launch(void* const* d_in, const int* in_sizes, int n_in,
                              void* d_out, int out_size) {
    const float* xs = (const float*)d_in[0];
    const float* ys = (const float*)d_in[1];
    float* out = (float*)d_out;

    sk_render_kernel<<<RGRID, BLOCK>>>(xs, ys, out);
    sk_normalize_kernel<<<(IM * IM) / (4 * NBLOCK), NBLOCK>>>(out);
}